// round 5
// baseline (speedup 1.0000x reference)
#include <cuda_runtime.h>
#include <cuda_bf16.h>
#include <math.h>
#include <stdint.h>

#define Q_LEN 2048
#define K_LEN 2048
#define BATCH 4
#define HEADS 8
#define EMB 512
#define INP 544
#define HD 32
#define BHN (BATCH*HEADS)

#define TQ 128
#define TK 128
#define NT (K_LEN/TK)
#define LDK 40          // smem tile row pitch in bf16 (80B -> conflict-free frag loads)

// projected q/k, bf16 hi/lo split, layout [bh][seq][32]
__device__ __nv_bfloat16 g_qh[(size_t)BHN * Q_LEN * HD];
__device__ __nv_bfloat16 g_ql[(size_t)BHN * Q_LEN * HD];
__device__ __nv_bfloat16 g_kh[(size_t)BHN * K_LEN * HD];
__device__ __nv_bfloat16 g_kl[(size_t)BHN * K_LEN * HD];
__device__ float g_pe[(size_t)Q_LEN * EMB];

// ───────────────────────── PE table ─────────────────────────
__global__ void pe_kernel() {
    int idx = blockIdx.x * 256 + threadIdx.x;
    int pos = idx >> 8;
    int i2  = idx & 255;
    float e = 2.0f * (float)i2;
    float div = expf(e * (-9.210340371976184f / 512.0f));
    float a = (float)pos * div;
    g_pe[(size_t)pos * EMB + 2 * i2]     = sinf(a);
    g_pe[(size_t)pos * EMB + 2 * i2 + 1] = cosf(a);
}

// ───────────────────────── projection ─────────────────────────
__global__ void __launch_bounds__(256, 2) proj_kernel(
        const float* __restrict__ qin, const float* __restrict__ kin,
        const float* __restrict__ Wq,  const float* __restrict__ bq,
        const float* __restrict__ Wk,  const float* __restrict__ bk) {
    __shared__ float As[32 * 36];
    __shared__ float Bs[32 * 256];

    const int is_q = (blockIdx.z == 0);
    const float* in   = is_q ? qin : kin;
    const float* W    = is_q ? Wq  : Wk;
    const float* bias = is_q ? bq  : bk;
    const int off     = is_q ? 0 : 256;
    __nv_bfloat16* oh = is_q ? g_qh : g_kh;
    __nv_bfloat16* ol = is_q ? g_ql : g_kl;

    int b  = blockIdx.y;
    int q0 = blockIdx.x * 32;
    int col = threadIdx.x;

    float acc[32];
    float bv = bias[off + col];
#pragma unroll
    for (int r = 0; r < 32; r++) acc[r] = bv;

    for (int et = 0; et < 16; et++) {
        {
            int i = threadIdx.x;
#pragma unroll
            for (int j = 0; j < 4; j++, i += 256) {
                int r = i >> 5, e = i & 31;
                int ge = et * 32 + e;
                float v = in[((size_t)(q0 + r) * BATCH + b) * EMB + ge];
                if (is_q) v += g_pe[(size_t)(q0 + r) * EMB + ge];
                As[r * 36 + e] = v;
            }
        }
#pragma unroll
        for (int e = 0; e < 32; e++)
            Bs[e * 256 + col] = W[(size_t)(et * 32 + e) * INP + off + col];
        __syncthreads();

#pragma unroll
        for (int e4 = 0; e4 < 8; e4++) {
            float b0 = Bs[(e4 * 4 + 0) * 256 + col];
            float b1 = Bs[(e4 * 4 + 1) * 256 + col];
            float b2 = Bs[(e4 * 4 + 2) * 256 + col];
            float b3 = Bs[(e4 * 4 + 3) * 256 + col];
#pragma unroll
            for (int r = 0; r < 32; r++) {
                float4 a4 = *(const float4*)&As[r * 36 + e4 * 4];
                acc[r] += a4.x * b0;
                acc[r] += a4.y * b1;
                acc[r] += a4.z * b2;
                acc[r] += a4.w * b3;
            }
        }
        __syncthreads();
    }

    int h = col >> 5, d = col & 31;
#pragma unroll
    for (int r = 0; r < 32; r++) {
        float v = acc[r];
        __nv_bfloat16 hi = __float2bfloat16(v);
        __nv_bfloat16 lo = __float2bfloat16(v - __bfloat162float(hi));
        size_t idx = ((size_t)(b * HEADS + h) * Q_LEN + (q0 + r)) * HD + d;
        oh[idx] = hi;
        ol[idx] = lo;
    }
}

// ───────────────────────── attention (mma.sync HMMA) ─────────────────────────
__device__ __forceinline__ void mma_bf16(float& d0, float& d1, float& d2, float& d3,
                                         const uint32_t a[4], const uint32_t b[2]) {
    asm volatile(
        "mma.sync.aligned.m16n8k16.row.col.f32.bf16.bf16.f32 "
        "{%0,%1,%2,%3}, {%4,%5,%6,%7}, {%8,%9}, {%0,%1,%2,%3};\n"
        : "+f"(d0), "+f"(d1), "+f"(d2), "+f"(d3)
        : "r"(a[0]), "r"(a[1]), "r"(a[2]), "r"(a[3]), "r"(b[0]), "r"(b[1]));
}

// smem layout (bytes): QH 0..10240, QL 10240..20480,
// Kbuf0 20480 (kh 10240 + kl 10240), Kbuf1 40960, KPM 61440..63488
#define OFF_QH   0
#define OFF_QL   10240
#define OFF_KB   20480
#define OFF_KPM  61440
#define SMEM_ATTN 63488

__global__ void __launch_bounds__(256, 2) attn_kernel(
        const unsigned char* __restrict__ am,
        const unsigned char* __restrict__ kpm,
        float* __restrict__ out) {
    extern __shared__ char smem[];
    __nv_bfloat16* qh_s = (__nv_bfloat16*)(smem + OFF_QH);
    __nv_bfloat16* ql_s = (__nv_bfloat16*)(smem + OFF_QL);
    unsigned char* kpm_s = (unsigned char*)(smem + OFF_KPM);

    int tid = threadIdx.x, w = tid >> 5, lane = tid & 31;
    int g = lane >> 2, qr = lane & 3;      // quad row / quad col
    int R0 = w * 16;                       // warp's q-row base (8 warps x 16 = 128)
    int bh = blockIdx.y, b = bh >> 3, h = bh & 7;
    int q0 = blockIdx.x * TQ;

    // load q tiles hi/lo (128 rows x 32 halfs = 512 uint4 each)
    {
#pragma unroll
        for (int j = 0; j < 2; j++) {
            int i = tid + j * 256;
            int r = i >> 2, c = i & 3;
            size_t gi = ((size_t)bh * Q_LEN + q0 + r) * 4 + c;
            *(uint4*)(qh_s + r * LDK + c * 8) = ((const uint4*)g_qh)[gi];
            *(uint4*)(ql_s + r * LDK + c * 8) = ((const uint4*)g_ql)[gi];
        }
    }
    if (tid < 128)
        ((uint4*)kpm_s)[tid] = ((const uint4*)(kpm + (size_t)b * K_LEN))[tid];
    __syncthreads();

    // A fragments (held for the whole kernel): rows R0+g / R0+g+8
    uint32_t aH[2][4], aL[2][4];
#pragma unroll
    for (int kc = 0; kc < 2; kc++) {
        int c0 = kc * 16 + qr * 2;
        aH[kc][0] = *(const uint32_t*)(qh_s + (R0 + g    ) * LDK + c0);
        aH[kc][1] = *(const uint32_t*)(qh_s + (R0 + g + 8) * LDK + c0);
        aH[kc][2] = *(const uint32_t*)(qh_s + (R0 + g    ) * LDK + c0 + 8);
        aH[kc][3] = *(const uint32_t*)(qh_s + (R0 + g + 8) * LDK + c0 + 8);
        aL[kc][0] = *(const uint32_t*)(ql_s + (R0 + g    ) * LDK + c0);
        aL[kc][1] = *(const uint32_t*)(ql_s + (R0 + g + 8) * LDK + c0);
        aL[kc][2] = *(const uint32_t*)(ql_s + (R0 + g    ) * LDK + c0 + 8);
        aL[kc][3] = *(const uint32_t*)(ql_s + (R0 + g + 8) * LDK + c0 + 8);
    }

    int r1 = R0 + g, r2 = r1 + 8;
    const unsigned char* am1 = am + (size_t)(q0 + r1) * K_LEN;
    const unsigned char* am2 = am + (size_t)(q0 + r2) * K_LEN;
    float* o1 = out + (((size_t)(h * BATCH + b)) * Q_LEN + q0 + r1) * K_LEN;
    float* o2 = out + (((size_t)(h * BATCH + b)) * Q_LEN + q0 + r2) * K_LEN;

    float inv1 = 1.f, inv2 = 1.f;

    for (int sweep = 0; sweep < 2; sweep++) {
        float s1 = 0.f, s2 = 0.f;
        // prologue: K tile 0 -> buf 0
        {
#pragma unroll
            for (int j = 0; j < 2; j++) {
                int i = tid + j * 256;
                int r = i >> 2, c = i & 3;
                size_t gi = ((size_t)bh * K_LEN + r) * 4 + c;
                *(uint4*)(smem + OFF_KB + (size_t)(r * LDK + c * 8) * 2) = ((const uint4*)g_kh)[gi];
                *(uint4*)(smem + OFF_KB + 10240 + (size_t)(r * LDK + c * 8) * 2) = ((const uint4*)g_kl)[gi];
            }
        }
        __syncthreads();

        for (int t = 0; t < NT; t++) {
            int cb = t & 1, nb = cb ^ 1;
            if (t + 1 < NT) {
#pragma unroll
                for (int j = 0; j < 2; j++) {
                    int i = tid + j * 256;
                    int r = i >> 2, c = i & 3;
                    size_t gi = ((size_t)bh * K_LEN + (t + 1) * TK + r) * 4 + c;
                    char* kb = smem + OFF_KB + nb * 20480;
                    *(uint4*)(kb + (size_t)(r * LDK + c * 8) * 2) = ((const uint4*)g_kh)[gi];
                    *(uint4*)(kb + 10240 + (size_t)(r * LDK + c * 8) * 2) = ((const uint4*)g_kl)[gi];
                }
            }
            const __nv_bfloat16* kh = (const __nv_bfloat16*)(smem + OFF_KB + cb * 20480);
            const __nv_bfloat16* kl = kh + 5120;   // 10240 bytes

#pragma unroll 2
            for (int nt = 0; nt < 16; nt++) {
                int n0 = nt * 8;
                uint32_t bH[2][2], bL[2][2];
#pragma unroll
                for (int kc = 0; kc < 2; kc++) {
                    int c0 = kc * 16 + qr * 2;
                    bH[kc][0] = *(const uint32_t*)(kh + (n0 + g) * LDK + c0);
                    bH[kc][1] = *(const uint32_t*)(kh + (n0 + g) * LDK + c0 + 8);
                    bL[kc][0] = *(const uint32_t*)(kl + (n0 + g) * LDK + c0);
                    bL[kc][1] = *(const uint32_t*)(kl + (n0 + g) * LDK + c0 + 8);
                }
                float d0 = 0.f, d1 = 0.f, d2 = 0.f, d3 = 0.f;
#pragma unroll
                for (int kc = 0; kc < 2; kc++) {
                    mma_bf16(d0, d1, d2, d3, aH[kc], bH[kc]);
                    mma_bf16(d0, d1, d2, d3, aH[kc], bL[kc]);
                    mma_bf16(d0, d1, d2, d3, aL[kc], bH[kc]);
                }
                // wait: B fragment col n = g -> output col = qr*2? No:
                // D col = (lane%4)*2 = qr*2 within the 8-wide n-tile; B col n = lane/4 = g.
                // Both mappings are consistent with PTX spec; output col index:
                int kg = t * TK + n0 + qr * 2;

                unsigned char p0 = kpm_s[kg], p1 = kpm_s[kg + 1];
                uchar2 m1 = *(const uchar2*)(am1 + kg);
                uchar2 m2 = *(const uchar2*)(am2 + kg);
                float e0 = (m1.x | p0) ? 0.f : __expf(d0);
                float e1 = (m1.y | p1) ? 0.f : __expf(d1);
                float e2 = (m2.x | p0) ? 0.f : __expf(d2);
                float e3 = (m2.y | p1) ? 0.f : __expf(d3);

                if (sweep == 0) {
                    s1 += e0 + e1;
                    s2 += e2 + e3;
                } else {
                    *(float2*)(o1 + kg) = make_float2(e0 * inv1, e1 * inv1);
                    *(float2*)(o2 + kg) = make_float2(e2 * inv2, e3 * inv2);
                }
            }
            __syncthreads();
        }

        if (sweep == 0) {
            // full row lives inside this warp: reduce over the quad (lanes sharing g)
            s1 += __shfl_xor_sync(0xffffffffu, s1, 1);
            s1 += __shfl_xor_sync(0xffffffffu, s1, 2);
            s2 += __shfl_xor_sync(0xffffffffu, s2, 1);
            s2 += __shfl_xor_sync(0xffffffffu, s2, 2);
            inv1 = 1.0f / s1;
            inv2 = 1.0f / s2;
        }
    }
}

extern "C" void kernel_launch(void* const* d_in, const int* in_sizes, int n_in,
                              void* d_out, int out_size) {
    const float* query = (const float*)d_in[0];
    const float* key   = (const float*)d_in[1];
    const float* Wq    = (const float*)d_in[2];
    const float* bq    = (const float*)d_in[3];
    const float* Wk    = (const float*)d_in[4];
    const float* bk    = (const float*)d_in[5];
    const unsigned char* kpm = (const unsigned char*)d_in[6];
    const unsigned char* amk = (const unsigned char*)d_in[7];
    float* out = (float*)d_out;

    cudaFuncSetAttribute(attn_kernel, cudaFuncAttributeMaxDynamicSharedMemorySize, SMEM_ATTN);

    pe_kernel<<<2048, 256>>>();
    proj_kernel<<<dim3(Q_LEN / 32, BATCH, 2), 256>>>(query, key, Wq, bq, Wk, bk);
    attn_kernel<<<dim3(Q_LEN / TQ, BHN), 256, SMEM_ATTN>>>(amk, kpm, out);
}